// round 1
// baseline (speedup 1.0000x reference)
#include <cuda_runtime.h>
#include <math.h>

// ============================================================================
// ContrastiveDistortion: fused pairwise-KL contrastive loss.
//
//   L[a,b] = D/(2T) - S[a,b]/(4T)
//   S[a,b] = P_a . Q_b + s_a + s_b          (rank-512 bilinear form)
//   result = mean_a( logsumexp_{b != a}(L[a,b] + to_add*[b==pos(a)]) - Lpos_a )
//
// Pipeline: feat_kernel -> gemm_softmax_kernel (fused online LSE) -> reduce.
// ============================================================================

namespace {
constexpr int BATCH = 2048;
constexpr int NROW  = 4096;       // 2*BATCH
constexpr int DIM   = 128;
constexpr int KF    = 512;        // 4 feature blocks of DIM
constexpr int NCHUNK = 8;         // column chunks (partial softmax)
constexpr int CPC   = NROW / NCHUNK;  // 512 cols per chunk
constexpr int BM = 64, BN = 64, BK = 16;

constexpr float C0 = 640.0f;      // D/(2T) = 128/0.2
constexpr float C1 = 2.5f;        // 1/(4T)
// to_add = -log((4095 - 1/5)/(4095 - 1)) = -log(4094.8/4094)
constexpr float TO_ADD = -1.9538888e-4f;
constexpr float NEG_BIG = -1e30f;
}

__device__ float g_P[NROW * KF];
__device__ float g_Q[NROW * KF];
__device__ float g_s[NROW];
__device__ float g_Lpos[NROW];
__device__ float g_partM[NCHUNK * NROW];
__device__ float g_partS[NCHUNK * NROW];

// ---------------------------------------------------------------------------
// Kernel 1: build feature matrices P, Q and row scalars s.
// grid = NROW blocks of DIM threads (one block per row).
// ---------------------------------------------------------------------------
__global__ void feat_kernel(const float* __restrict__ mu_x,
                            const float* __restrict__ sig_x,
                            const float* __restrict__ mu_p,
                            const float* __restrict__ sig_p) {
    const int i = blockIdx.x;   // row
    const int d = threadIdx.x;  // dim

    const float* mu_src = (i < BATCH) ? mu_x + (size_t)i * DIM
                                      : mu_p + (size_t)(i - BATCH) * DIM;
    const float* sg_src = (i < BATCH) ? sig_x + (size_t)i * DIM
                                      : sig_p + (size_t)(i - BATCH) * DIM;
    const float mu  = mu_src[d];
    const float sg  = sg_src[d];
    const float var = sg * sg;
    const float inv = 1.0f / var;
    const float mu2 = mu * mu;

    const size_t base = (size_t)i * KF;
    g_P[base +   0 + d] = inv;
    g_P[base + 128 + d] = var + mu2;
    g_P[base + 256 + d] = mu * inv;
    g_P[base + 384 + d] = mu;

    g_Q[base +   0 + d] = var + mu2;
    g_Q[base + 128 + d] = inv;
    g_Q[base + 256 + d] = -2.0f * mu;
    g_Q[base + 384 + d] = -2.0f * mu * inv;

    __shared__ float red[DIM];
    red[d] = mu2 * inv;
    __syncthreads();
    #pragma unroll
    for (int off = 64; off > 0; off >>= 1) {
        if (d < off) red[d] += red[d + off];
        __syncthreads();
    }
    if (d == 0) g_s[i] = red[0];
}

// ---------------------------------------------------------------------------
// Kernel 2: tiled fp32 GEMM (S = P.Q^T) fused with online logsumexp per row.
// grid = (NCHUNK, NROW/BM), 256 threads, 4x4 micro-tile per thread.
// Each block owns BM rows x CPC columns; emits one (max,sum) partial per row.
// ---------------------------------------------------------------------------
__global__ __launch_bounds__(256, 2) void gemm_softmax_kernel() {
    const int chunk   = blockIdx.x;
    const int rowBase = blockIdx.y * BM;
    const int tid = threadIdx.x;
    const int tx = tid & 15;    // column group
    const int ty = tid >> 4;    // row group

    __shared__ float As[BK][BM];
    __shared__ float Bs[BK][BN];
    __shared__ float redM[BM][16];
    __shared__ float redS[BM][16];

    float m[4], su[4], sr[4];
    int rowIdx[4], posR[4];
    #pragma unroll
    for (int r = 0; r < 4; ++r) {
        rowIdx[r] = rowBase + ty * 4 + r;
        m[r] = NEG_BIG;
        su[r] = 0.0f;
        sr[r] = g_s[rowIdx[r]];
        posR[r] = (rowIdx[r] < BATCH) ? rowIdx[r] + BATCH : rowIdx[r] - BATCH;
    }

    const int aRow = tid >> 2;          // 0..63
    const int aK   = (tid & 3) * 4;     // 0,4,8,12

    for (int ct = 0; ct < CPC / BN; ++ct) {
        const int colBase = chunk * CPC + ct * BN;

        float acc[4][4];
        #pragma unroll
        for (int r = 0; r < 4; ++r)
            #pragma unroll
            for (int c = 0; c < 4; ++c) acc[r][c] = 0.0f;

        for (int kt = 0; kt < KF; kt += BK) {
            const float4 av = *reinterpret_cast<const float4*>(
                &g_P[(size_t)(rowBase + aRow) * KF + kt + aK]);
            const float4 bv = *reinterpret_cast<const float4*>(
                &g_Q[(size_t)(colBase + aRow) * KF + kt + aK]);
            __syncthreads();   // previous tile's reads done before overwrite
            As[aK + 0][aRow] = av.x; As[aK + 1][aRow] = av.y;
            As[aK + 2][aRow] = av.z; As[aK + 3][aRow] = av.w;
            Bs[aK + 0][aRow] = bv.x; Bs[aK + 1][aRow] = bv.y;
            Bs[aK + 2][aRow] = bv.z; Bs[aK + 3][aRow] = bv.w;
            __syncthreads();

            #pragma unroll
            for (int k = 0; k < BK; ++k) {
                const float4 a = *reinterpret_cast<const float4*>(&As[k][ty * 4]);
                const float4 b = *reinterpret_cast<const float4*>(&Bs[k][tx * 4]);
                const float ar[4] = {a.x, a.y, a.z, a.w};
                const float br[4] = {b.x, b.y, b.z, b.w};
                #pragma unroll
                for (int r = 0; r < 4; ++r)
                    #pragma unroll
                    for (int c = 0; c < 4; ++c)
                        acc[r][c] = fmaf(ar[r], br[c], acc[r][c]);
            }
        }

        // Epilogue: convert to logits, online (max,sumexp) update per row.
        #pragma unroll
        for (int c = 0; c < 4; ++c) {
            const int col = colBase + tx * 4 + c;
            const float sc = g_s[col];
            #pragma unroll
            for (int r = 0; r < 4; ++r) {
                if (col == rowIdx[r]) continue;           // drop diagonal
                float v = C0 - (acc[r][c] + sr[r] + sc) * C1;
                if (col == posR[r]) {                     // positive logit
                    v += TO_ADD;
                    g_Lpos[rowIdx[r]] = v;
                }
                const float nm = fmaxf(m[r], v);
                su[r] = su[r] * __expf(m[r] - nm) + __expf(v - nm);
                m[r] = nm;
            }
        }
    }

    // Reduce (max,sum) across the 16 threads sharing each row.
    __syncthreads();
    #pragma unroll
    for (int r = 0; r < 4; ++r) {
        redM[ty * 4 + r][tx] = m[r];
        redS[ty * 4 + r][tx] = su[r];
    }
    __syncthreads();
    if (tid < BM) {
        float M = NEG_BIG, S = 0.0f;
        #pragma unroll
        for (int j = 0; j < 16; ++j) {
            const float mj = redM[tid][j];
            const float sj = redS[tid][j];
            const float nm = fmaxf(M, mj);
            S = S * __expf(M - nm) + sj * __expf(mj - nm);
            M = nm;
        }
        g_partM[chunk * NROW + rowBase + tid] = M;
        g_partS[chunk * NROW + rowBase + tid] = S;
    }
}

// ---------------------------------------------------------------------------
// Kernel 3: merge chunk partials -> per-row LSE -> mean(lse - Lpos).
// ---------------------------------------------------------------------------
__global__ void reduce_kernel(float* __restrict__ out) {
    __shared__ float red[256];
    const int tid = threadIdx.x;
    float local = 0.0f;
    for (int row = tid; row < NROW; row += 256) {
        float M = NEG_BIG, S = 0.0f;
        #pragma unroll
        for (int ch = 0; ch < NCHUNK; ++ch) {
            const float mj = g_partM[ch * NROW + row];
            const float sj = g_partS[ch * NROW + row];
            const float nm = fmaxf(M, mj);
            S = S * expf(M - nm) + sj * expf(mj - nm);
            M = nm;
        }
        const float lse = M + logf(S);
        local += lse - g_Lpos[row];
    }
    red[tid] = local;
    __syncthreads();
    #pragma unroll
    for (int off = 128; off > 0; off >>= 1) {
        if (tid < off) red[tid] += red[tid + off];
        __syncthreads();
    }
    if (tid == 0) out[0] = red[0] / (float)NROW;
}

// ---------------------------------------------------------------------------
extern "C" void kernel_launch(void* const* d_in, const int* in_sizes, int n_in,
                              void* d_out, int out_size) {
    (void)in_sizes; (void)n_in; (void)out_size;
    // metadata order: z_hat (unused), mu_x, sigma_x, mu_p, sigma_p
    const float* mu_x  = (const float*)d_in[1];
    const float* sig_x = (const float*)d_in[2];
    const float* mu_p  = (const float*)d_in[3];
    const float* sig_p = (const float*)d_in[4];
    float* out = (float*)d_out;

    feat_kernel<<<NROW, DIM>>>(mu_x, sig_x, mu_p, sig_p);
    gemm_softmax_kernel<<<dim3(NCHUNK, NROW / BM), 256>>>();
    reduce_kernel<<<1, 256>>>(out);
}

// round 3
// speedup vs baseline: 3.2820x; 3.2820x over previous
#include <cuda_runtime.h>
#include <cuda_bf16.h>
#include <stdint.h>
#include <math.h>

// ============================================================================
// ContrastiveDistortion:
//   logits[a,b] = C0 - C1*(P_a.Q_b + s_a + s_b)   (rank-512 symmetric bilinear)
//   fp32 emulated with bf16x3: P' = [Ph|Ph|Pl] (K=1536), Q' = [Qh|Ql|Qh].
// Pipeline: feat -> mma.sync bf16 GEMM fused with online logsumexp -> reduce.
// (tcgen05 unavailable: harness PTX target is compute_100, not compute_100a.)
// ============================================================================

namespace {
constexpr int BATCH = 2048;
constexpr int NROW  = 4096;
constexpr int DIM   = 128;
constexpr int KF3   = 1536;           // 3 * 512
constexpr int NBLK  = 32;             // 4096 / 128 row & col blocks
constexpr int BK    = 64;             // k elements per stage
constexpr int KSTAGES = KF3 / BK;     // 24
constexpr int ROWBYTES = KF3 * 2;     // 3072

constexpr float C0 = 640.0f;          // D/(2T)
constexpr float C1 = 2.5f;            // 1/(4T)
constexpr float TO_ADD = -1.9538879e-4f;
constexpr float NEG_BIG = -1e30f;
}

__device__ __nv_bfloat16 g_P[(size_t)NROW * KF3];   // 12.6 MB
__device__ __nv_bfloat16 g_Q[(size_t)NROW * KF3];   // 12.6 MB
__device__ float g_s[NROW];
__device__ float g_Lpos[NROW];
__device__ float g_partM[NBLK * NROW];
__device__ float g_partS[NBLK * NROW];

// ---------------------------------------------------------------------------
// helpers
// ---------------------------------------------------------------------------
__device__ __forceinline__ uint32_t smem_u32(const void* p) {
    uint32_t a;
    asm("{ .reg .u64 t; cvta.to.shared.u64 t, %1; cvt.u32.u64 %0, t; }" : "=r"(a) : "l"(p));
    return a;
}
__device__ __forceinline__ void cpasync16(uint32_t dst, const void* src) {
    asm volatile("cp.async.cg.shared.global [%0], [%1], 16;" :: "r"(dst), "l"(src) : "memory");
}
__device__ __forceinline__ void ldsm_x4(uint32_t* r, uint32_t addr) {
    asm volatile("ldmatrix.sync.aligned.m8n8.x4.shared.b16 {%0,%1,%2,%3}, [%4];"
                 : "=r"(r[0]), "=r"(r[1]), "=r"(r[2]), "=r"(r[3]) : "r"(addr));
}
__device__ __forceinline__ void mma16816(float* d, const uint32_t* a, uint32_t b0, uint32_t b1) {
    asm volatile(
        "mma.sync.aligned.m16n8k16.row.col.f32.bf16.bf16.f32 "
        "{%0,%1,%2,%3}, {%4,%5,%6,%7}, {%8,%9}, {%0,%1,%2,%3};"
        : "+f"(d[0]), "+f"(d[1]), "+f"(d[2]), "+f"(d[3])
        : "r"(a[0]), "r"(a[1]), "r"(a[2]), "r"(a[3]), "r"(b0), "r"(b1));
}

// ---------------------------------------------------------------------------
// Kernel 1: build bf16x3 feature rows (row-major) + row scalars s.
// One block handles 2 rows; thread t: row = 2*bid + (t>>6), dims 2*(t&63)+{0,1}.
// ---------------------------------------------------------------------------
__global__ void feat_kernel(const float* __restrict__ mu_x,
                            const float* __restrict__ sig_x,
                            const float* __restrict__ mu_p,
                            const float* __restrict__ sig_p) {
    const int t = threadIdx.x;
    const int row = blockIdx.x * 2 + (t >> 6);
    const int d2 = t & 63;

    const float* mu_src = (row < BATCH) ? mu_x + (size_t)row * DIM
                                        : mu_p + (size_t)(row - BATCH) * DIM;
    const float* sg_src = (row < BATCH) ? sig_x + (size_t)row * DIM
                                        : sig_p + (size_t)(row - BATCH) * DIM;
    const float2 mu = *reinterpret_cast<const float2*>(mu_src + 2 * d2);
    const float2 sg = *reinterpret_cast<const float2*>(sg_src + 2 * d2);

    const float var0 = sg.x * sg.x, inv0 = 1.0f / var0;
    const float var1 = sg.y * sg.y, inv1 = 1.0f / var1;
    const float w0 = var0 + mu.x * mu.x, w1 = var1 + mu.y * mu.y;
    const float t0 = mu.x * inv0, t1 = mu.y * inv1;

    // P feature blocks {inv, w, t, mu};  Q blocks {w, inv, -2mu, -2t}
    const float Pf[4][2] = {{inv0, inv1}, {w0, w1}, {t0, t1}, {mu.x, mu.y}};
    const float Qf[4][2] = {{w0, w1}, {inv0, inv1}, {-2.0f * mu.x, -2.0f * mu.y},
                            {-2.0f * t0, -2.0f * t1}};

    __nv_bfloat16* Prow = g_P + (size_t)row * KF3;
    __nv_bfloat16* Qrow = g_Q + (size_t)row * KF3;

    #pragma unroll
    for (int blk = 0; blk < 4; ++blk) {
        const int k0 = blk * 128 + 2 * d2;
        // P: hi | hi | lo
        {
            const float x0 = Pf[blk][0], x1 = Pf[blk][1];
            __nv_bfloat16 h0 = __float2bfloat16(x0), h1 = __float2bfloat16(x1);
            __nv_bfloat16 l0 = __float2bfloat16(x0 - __bfloat162float(h0));
            __nv_bfloat16 l1 = __float2bfloat16(x1 - __bfloat162float(h1));
            __nv_bfloat162 hp = {h0, h1}, lp = {l0, l1};
            const uint32_t hip = *reinterpret_cast<uint32_t*>(&hp);
            const uint32_t lop = *reinterpret_cast<uint32_t*>(&lp);
            *reinterpret_cast<uint32_t*>(Prow +    0 + k0) = hip;
            *reinterpret_cast<uint32_t*>(Prow +  512 + k0) = hip;
            *reinterpret_cast<uint32_t*>(Prow + 1024 + k0) = lop;
        }
        // Q: hi | lo | hi
        {
            const float x0 = Qf[blk][0], x1 = Qf[blk][1];
            __nv_bfloat16 h0 = __float2bfloat16(x0), h1 = __float2bfloat16(x1);
            __nv_bfloat16 l0 = __float2bfloat16(x0 - __bfloat162float(h0));
            __nv_bfloat16 l1 = __float2bfloat16(x1 - __bfloat162float(h1));
            __nv_bfloat162 hp = {h0, h1}, lp = {l0, l1};
            const uint32_t hip = *reinterpret_cast<uint32_t*>(&hp);
            const uint32_t lop = *reinterpret_cast<uint32_t*>(&lp);
            *reinterpret_cast<uint32_t*>(Qrow +    0 + k0) = hip;
            *reinterpret_cast<uint32_t*>(Qrow +  512 + k0) = lop;
            *reinterpret_cast<uint32_t*>(Qrow + 1024 + k0) = hip;
        }
    }

    // s = sum_d mu^2 / var
    float part = t0 * mu.x + t1 * mu.y;
    #pragma unroll
    for (int o = 16; o > 0; o >>= 1) part += __shfl_down_sync(0xffffffffu, part, o);
    __shared__ float ws[4];
    if ((t & 31) == 0) ws[t >> 5] = part;
    __syncthreads();
    if ((t & 63) == 0) g_s[row] = ws[t >> 5] + ws[(t >> 5) + 1];
}

// ---------------------------------------------------------------------------
// Kernel 2: 128x128x1536 bf16 mma.sync GEMM per CTA, fused online LSE.
// grid = (32, 32), 256 threads (8 warps, wm in {0,1} x wn in {0..3}).
// Dynamic smem: A stages 2x16KB, B stages 2x16KB (XOR-swizzled).
// ---------------------------------------------------------------------------
__global__ __launch_bounds__(256) void gemm_kernel() {
    extern __shared__ char smem[];
    __shared__ float scol[128], srow[128];
    __shared__ float redM[128][4], redS[128][4];

    const int tid = threadIdx.x;
    const int lane = tid & 31;
    const int warp = tid >> 5;
    const int wm = warp >> 2;      // 0..1 (m-half)
    const int wn = warp & 3;       // 0..3 (n-quarter)
    const int colBlk = blockIdx.x, rowBlk = blockIdx.y;
    const int rowBase = rowBlk * 128, colBase = colBlk * 128;

    if (tid < 128) {
        srow[tid] = g_s[rowBase + tid];
        scol[tid] = g_s[colBase + tid];
    }

    const uint32_t sb = smem_u32(smem);
    const char* gA = (const char*)g_P + (size_t)rowBase * ROWBYTES;
    const char* gB = (const char*)g_Q + (size_t)colBase * ROWBYTES;

    float acc[4][4][4];
    #pragma unroll
    for (int mt = 0; mt < 4; ++mt)
        #pragma unroll
        for (int nt = 0; nt < 4; ++nt)
            #pragma unroll
            for (int j = 0; j < 4; ++j) acc[mt][nt][j] = 0.0f;

    // lane-derived ldmatrix address components
    const int l15 = lane & 15, lh = lane >> 4;
    const uint32_t xmask = (uint32_t)(lane & 7) << 4;
    uint32_t rowOffA[4], rowOffB[2], kx[4];
    #pragma unroll
    for (int mt = 0; mt < 4; ++mt) rowOffA[mt] = (uint32_t)(wm * 64 + mt * 16 + l15) * 128u;
    #pragma unroll
    for (int np = 0; np < 2; ++np) rowOffB[np] = (uint32_t)(wn * 32 + np * 16 + l15) * 128u;
    #pragma unroll
    for (int ks = 0; ks < 4; ++ks) kx[ks] = ((uint32_t)(ks * 32 + lh * 16)) ^ xmask;

    // cp.async stage loader: 128 rows x 8 x 16B per operand, 4 chunks/thread each
    auto load_stage = [&](int kt, int s) {
        const uint32_t aD = sb + (uint32_t)s * 16384u;
        const uint32_t bD = sb + 32768u + (uint32_t)s * 16384u;
        #pragma unroll
        for (int i = 0; i < 4; ++i) {
            const int id = tid + 256 * i;
            const int r = id >> 3, l8 = id & 7;
            const uint32_t doff = (uint32_t)r * 128u + (uint32_t)((l8 ^ (r & 7)) << 4);
            const size_t soff = (size_t)r * ROWBYTES + (size_t)kt * 128 + (size_t)l8 * 16;
            cpasync16(aD + doff, gA + soff);
            cpasync16(bD + doff, gB + soff);
        }
        asm volatile("cp.async.commit_group;" ::: "memory");
    };

    load_stage(0, 0);
    for (int kt = 0; kt < KSTAGES; ++kt) {
        const int s = kt & 1;
        if (kt + 1 < KSTAGES) {
            load_stage(kt + 1, (kt + 1) & 1);
            asm volatile("cp.async.wait_group 1;" ::: "memory");
        } else {
            asm volatile("cp.async.wait_group 0;" ::: "memory");
        }
        __syncthreads();

        const uint32_t aB = sb + (uint32_t)s * 16384u;
        const uint32_t bB = sb + 32768u + (uint32_t)s * 16384u;
        #pragma unroll
        for (int ks = 0; ks < 4; ++ks) {
            uint32_t a[4][4], bt[2][4];
            #pragma unroll
            for (int mt = 0; mt < 4; ++mt) ldsm_x4(a[mt], aB + rowOffA[mt] + kx[ks]);
            #pragma unroll
            for (int np = 0; np < 2; ++np) ldsm_x4(bt[np], bB + rowOffB[np] + kx[ks]);
            #pragma unroll
            for (int mt = 0; mt < 4; ++mt)
                #pragma unroll
                for (int nt = 0; nt < 4; ++nt)
                    mma16816(acc[mt][nt], a[mt], bt[nt >> 1][nt & 1], bt[nt >> 1][(nt & 1) + 2]);
        }
        __syncthreads();
    }

    // ---- epilogue: logits + fused online LSE ----
    const int qrow = lane >> 2;          // row within 8-group
    const int qc = (lane & 3) * 2;       // col pair base

    #pragma unroll
    for (int mt = 0; mt < 4; ++mt) {
        #pragma unroll
        for (int half = 0; half < 2; ++half) {
            const int rl = wm * 64 + mt * 16 + half * 8 + qrow;
            const int grow = rowBase + rl;
            const float sr = srow[rl];
            const int posR = (grow < BATCH) ? grow + BATCH : grow - BATCH;

            float v[8];
            #pragma unroll
            for (int nt = 0; nt < 4; ++nt) {
                const int cl = wn * 32 + nt * 8 + qc;
                #pragma unroll
                for (int j = 0; j < 2; ++j) {
                    const int col = colBase + cl + j;
                    float val = C0 - C1 * (acc[mt][nt][half * 2 + j] + sr + scol[cl + j]);
                    if (col == grow) {
                        val = NEG_BIG;
                    } else if (col == posR) {
                        val += TO_ADD;
                        g_Lpos[grow] = val;
                    }
                    v[nt * 2 + j] = val;
                }
            }
            float m = v[0];
            #pragma unroll
            for (int j = 1; j < 8; ++j) m = fmaxf(m, v[j]);
            float su = 0.0f;
            #pragma unroll
            for (int j = 0; j < 8; ++j) su += __expf(v[j] - m);
            // reduce across the 4 lanes of the quad (same row, different cols)
            #pragma unroll
            for (int o = 1; o < 4; o <<= 1) {
                const float mo = __shfl_xor_sync(0xffffffffu, m, o);
                const float so = __shfl_xor_sync(0xffffffffu, su, o);
                const float nm = fmaxf(m, mo);
                su = su * __expf(m - nm) + so * __expf(mo - nm);
                m = nm;
            }
            if ((lane & 3) == 0) { redM[rl][wn] = m; redS[rl][wn] = su; }
        }
    }
    __syncthreads();

    if (tid < 128) {
        float M = redM[tid][0], S = redS[tid][0];
        #pragma unroll
        for (int j = 1; j < 4; ++j) {
            const float mj = redM[tid][j], sj = redS[tid][j];
            const float nm = fmaxf(M, mj);
            S = S * __expf(M - nm) + sj * __expf(mj - nm);
            M = nm;
        }
        g_partM[colBlk * NROW + rowBase + tid] = M;
        g_partS[colBlk * NROW + rowBase + tid] = S;
    }
}

// ---------------------------------------------------------------------------
// Kernel 3: merge 32 chunk partials per row -> LSE -> mean(lse - Lpos).
// ---------------------------------------------------------------------------
__global__ void reduce_kernel(float* __restrict__ out) {
    __shared__ float red[256];
    const int tid = threadIdx.x;
    float local = 0.0f;
    for (int row = tid; row < NROW; row += 256) {
        float M = NEG_BIG, S = 0.0f;
        #pragma unroll
        for (int ch = 0; ch < NBLK; ++ch) {
            const float mj = g_partM[ch * NROW + row];
            const float sj = g_partS[ch * NROW + row];
            const float nm = fmaxf(M, mj);
            S = S * expf(M - nm) + sj * expf(mj - nm);
            M = nm;
        }
        local += (M + logf(S)) - g_Lpos[row];
    }
    red[tid] = local;
    __syncthreads();
    #pragma unroll
    for (int off = 128; off > 0; off >>= 1) {
        if (tid < off) red[tid] += red[tid + off];
        __syncthreads();
    }
    if (tid == 0) out[0] = red[0] / (float)NROW;
}

// ---------------------------------------------------------------------------
extern "C" void kernel_launch(void* const* d_in, const int* in_sizes, int n_in,
                              void* d_out, int out_size) {
    (void)in_sizes; (void)n_in; (void)out_size;
    const float* mu_x  = (const float*)d_in[1];
    const float* sig_x = (const float*)d_in[2];
    const float* mu_p  = (const float*)d_in[3];
    const float* sig_p = (const float*)d_in[4];
    float* out = (float*)d_out;

    static bool attr_set = false;
    if (!attr_set) {
        cudaFuncSetAttribute(gemm_kernel, cudaFuncAttributeMaxDynamicSharedMemorySize, 65536);
        attr_set = true;
    }

    feat_kernel<<<NROW / 2, 128>>>(mu_x, sig_x, mu_p, sig_p);
    gemm_kernel<<<dim3(NBLK, NBLK), 256, 65536>>>();
    reduce_kernel<<<1, 256>>>(out);
}

// round 4
// speedup vs baseline: 4.6022x; 1.4023x over previous
#include <cuda_runtime.h>
#include <cuda_bf16.h>
#include <stdint.h>
#include <math.h>

// ============================================================================
// ContrastiveDistortion:
//   logits[a,b] = C0 - C1*(P_a.Q_b + s_a + s_b)   (rank-512 SYMMETRIC bilinear)
//   fp32 emulated with bf16x3: P' = [Ph|Ph|Pl] (K=1536), Q' = [Qh|Ql|Qh].
// Symmetry: S[a,b]==S[b,a] -> compute only upper-triangular 128x128 blocks
// (528 of 1024); each off-diag tile feeds row-wise AND column-wise online LSE.
// ============================================================================

namespace {
constexpr int BATCH = 2048;
constexpr int NROW  = 4096;
constexpr int DIM   = 128;
constexpr int KF3   = 1536;           // 3 * 512
constexpr int NBLK  = 32;             // 4096 / 128
constexpr int NPAIR = NBLK * (NBLK + 1) / 2;   // 528
constexpr int KSTAGES = KF3 / 64;     // 24
constexpr int ROWBYTES = KF3 * 2;     // 3072

constexpr float C0 = 640.0f;          // D/(2T)
constexpr float C1 = 2.5f;            // 1/(4T)
constexpr float TO_ADD = -1.9538879e-4f;
constexpr float NEG_BIG = -1e30f;
}

__device__ __nv_bfloat16 g_P[(size_t)NROW * KF3];   // 12.6 MB
__device__ __nv_bfloat16 g_Q[(size_t)NROW * KF3];   // 12.6 MB
__device__ float g_s[NROW];
__device__ float g_Lpos[NROW];
__device__ float g_partM[NBLK * NROW];
__device__ float g_partS[NBLK * NROW];

// ---------------------------------------------------------------------------
// helpers
// ---------------------------------------------------------------------------
__device__ __forceinline__ uint32_t smem_u32(const void* p) {
    uint32_t a;
    asm("{ .reg .u64 t; cvta.to.shared.u64 t, %1; cvt.u32.u64 %0, t; }" : "=r"(a) : "l"(p));
    return a;
}
__device__ __forceinline__ void cpasync16(uint32_t dst, const void* src) {
    asm volatile("cp.async.cg.shared.global [%0], [%1], 16;" :: "r"(dst), "l"(src) : "memory");
}
__device__ __forceinline__ void ldsm_x4(uint32_t* r, uint32_t addr) {
    asm volatile("ldmatrix.sync.aligned.m8n8.x4.shared.b16 {%0,%1,%2,%3}, [%4];"
                 : "=r"(r[0]), "=r"(r[1]), "=r"(r[2]), "=r"(r[3]) : "r"(addr));
}
__device__ __forceinline__ void mma16816(float* d, const uint32_t* a, uint32_t b0, uint32_t b1) {
    asm volatile(
        "mma.sync.aligned.m16n8k16.row.col.f32.bf16.bf16.f32 "
        "{%0,%1,%2,%3}, {%4,%5,%6,%7}, {%8,%9}, {%0,%1,%2,%3};"
        : "+f"(d[0]), "+f"(d[1]), "+f"(d[2]), "+f"(d[3])
        : "r"(a[0]), "r"(a[1]), "r"(a[2]), "r"(a[3]), "r"(b0), "r"(b1));
}

// ---------------------------------------------------------------------------
// Kernel 1: build bf16x3 feature rows + row scalars s.
// ---------------------------------------------------------------------------
__global__ void feat_kernel(const float* __restrict__ mu_x,
                            const float* __restrict__ sig_x,
                            const float* __restrict__ mu_p,
                            const float* __restrict__ sig_p) {
    const int t = threadIdx.x;
    const int row = blockIdx.x * 2 + (t >> 6);
    const int d2 = t & 63;

    const float* mu_src = (row < BATCH) ? mu_x + (size_t)row * DIM
                                        : mu_p + (size_t)(row - BATCH) * DIM;
    const float* sg_src = (row < BATCH) ? sig_x + (size_t)row * DIM
                                        : sig_p + (size_t)(row - BATCH) * DIM;
    const float2 mu = *reinterpret_cast<const float2*>(mu_src + 2 * d2);
    const float2 sg = *reinterpret_cast<const float2*>(sg_src + 2 * d2);

    const float var0 = sg.x * sg.x, inv0 = 1.0f / var0;
    const float var1 = sg.y * sg.y, inv1 = 1.0f / var1;
    const float w0 = var0 + mu.x * mu.x, w1 = var1 + mu.y * mu.y;
    const float t0 = mu.x * inv0, t1 = mu.y * inv1;

    const float Pf[4][2] = {{inv0, inv1}, {w0, w1}, {t0, t1}, {mu.x, mu.y}};
    const float Qf[4][2] = {{w0, w1}, {inv0, inv1}, {-2.0f * mu.x, -2.0f * mu.y},
                            {-2.0f * t0, -2.0f * t1}};

    __nv_bfloat16* Prow = g_P + (size_t)row * KF3;
    __nv_bfloat16* Qrow = g_Q + (size_t)row * KF3;

    #pragma unroll
    for (int blk = 0; blk < 4; ++blk) {
        const int k0 = blk * 128 + 2 * d2;
        {
            const float x0 = Pf[blk][0], x1 = Pf[blk][1];
            __nv_bfloat16 h0 = __float2bfloat16(x0), h1 = __float2bfloat16(x1);
            __nv_bfloat16 l0 = __float2bfloat16(x0 - __bfloat162float(h0));
            __nv_bfloat16 l1 = __float2bfloat16(x1 - __bfloat162float(h1));
            __nv_bfloat162 hp = {h0, h1}, lp = {l0, l1};
            const uint32_t hip = *reinterpret_cast<uint32_t*>(&hp);
            const uint32_t lop = *reinterpret_cast<uint32_t*>(&lp);
            *reinterpret_cast<uint32_t*>(Prow +    0 + k0) = hip;
            *reinterpret_cast<uint32_t*>(Prow +  512 + k0) = hip;
            *reinterpret_cast<uint32_t*>(Prow + 1024 + k0) = lop;
        }
        {
            const float x0 = Qf[blk][0], x1 = Qf[blk][1];
            __nv_bfloat16 h0 = __float2bfloat16(x0), h1 = __float2bfloat16(x1);
            __nv_bfloat16 l0 = __float2bfloat16(x0 - __bfloat162float(h0));
            __nv_bfloat16 l1 = __float2bfloat16(x1 - __bfloat162float(h1));
            __nv_bfloat162 hp = {h0, h1}, lp = {l0, l1};
            const uint32_t hip = *reinterpret_cast<uint32_t*>(&hp);
            const uint32_t lop = *reinterpret_cast<uint32_t*>(&lp);
            *reinterpret_cast<uint32_t*>(Qrow +    0 + k0) = hip;
            *reinterpret_cast<uint32_t*>(Qrow +  512 + k0) = lop;
            *reinterpret_cast<uint32_t*>(Qrow + 1024 + k0) = hip;
        }
    }

    float part = t0 * mu.x + t1 * mu.y;
    #pragma unroll
    for (int o = 16; o > 0; o >>= 1) part += __shfl_down_sync(0xffffffffu, part, o);
    __shared__ float ws[4];
    if ((t & 31) == 0) ws[t >> 5] = part;
    __syncthreads();
    if ((t & 63) == 0) g_s[row] = ws[t >> 5] + ws[(t >> 5) + 1];
}

// ---------------------------------------------------------------------------
// Kernel 2: upper-triangular 128x128x1536 bf16 mma.sync GEMM, fused dual LSE.
// grid = 528 (pairs i<=j), 256 threads (8 warps: wm in {0,1} x wn in {0..3}).
// ---------------------------------------------------------------------------
__global__ __launch_bounds__(256) void gemm_kernel() {
    extern __shared__ char smem[];
    __shared__ float scol[128], srow[128];
    __shared__ float redM[128][4], redS[128][4];     // row-side across wn
    __shared__ float redCM[128][2], redCS[128][2];   // col-side across wm

    const int tid = threadIdx.x;
    const int lane = tid & 31;
    const int warp = tid >> 5;
    const int wm = warp >> 2;
    const int wn = warp & 3;

    // triangular decode: bid -> (i, j), i <= j
    int i = 0, tt = blockIdx.x;
    while (tt >= NBLK - i) { tt -= NBLK - i; ++i; }
    const int j = i + tt;
    const bool isDiag = (i == j);
    const bool isPair = (j == i + 16);     // positives on the tile diagonal
    const int rowBase = i * 128, colBase = j * 128;

    if (tid < 128) {
        srow[tid] = g_s[rowBase + tid];
        scol[tid] = g_s[colBase + tid];
    }

    const uint32_t sb = smem_u32(smem);
    const char* gA = (const char*)g_P + (size_t)rowBase * ROWBYTES;
    const char* gB = (const char*)g_Q + (size_t)colBase * ROWBYTES;

    float acc[4][4][4];
    #pragma unroll
    for (int mt = 0; mt < 4; ++mt)
        #pragma unroll
        for (int nt = 0; nt < 4; ++nt)
            #pragma unroll
            for (int e = 0; e < 4; ++e) acc[mt][nt][e] = 0.0f;

    const int l15 = lane & 15, lh = lane >> 4;
    const uint32_t xmask = (uint32_t)(lane & 7) << 4;
    uint32_t rowOffA[4], rowOffB[2], kx[4];
    #pragma unroll
    for (int mt = 0; mt < 4; ++mt) rowOffA[mt] = (uint32_t)(wm * 64 + mt * 16 + l15) * 128u;
    #pragma unroll
    for (int np = 0; np < 2; ++np) rowOffB[np] = (uint32_t)(wn * 32 + np * 16 + l15) * 128u;
    #pragma unroll
    for (int ks = 0; ks < 4; ++ks) kx[ks] = ((uint32_t)(ks * 32 + lh * 16)) ^ xmask;

    auto load_stage = [&](int kt, int s) {
        const uint32_t aD = sb + (uint32_t)s * 16384u;
        const uint32_t bD = sb + 32768u + (uint32_t)s * 16384u;
        #pragma unroll
        for (int u = 0; u < 4; ++u) {
            const int id = tid + 256 * u;
            const int r = id >> 3, l8 = id & 7;
            const uint32_t doff = (uint32_t)r * 128u + (uint32_t)((l8 ^ (r & 7)) << 4);
            const size_t soff = (size_t)r * ROWBYTES + (size_t)kt * 128 + (size_t)l8 * 16;
            cpasync16(aD + doff, gA + soff);
            cpasync16(bD + doff, gB + soff);
        }
        asm volatile("cp.async.commit_group;" ::: "memory");
    };

    load_stage(0, 0);
    for (int kt = 0; kt < KSTAGES; ++kt) {
        const int s = kt & 1;
        if (kt + 1 < KSTAGES) {
            load_stage(kt + 1, (kt + 1) & 1);
            asm volatile("cp.async.wait_group 1;" ::: "memory");
        } else {
            asm volatile("cp.async.wait_group 0;" ::: "memory");
        }
        __syncthreads();

        const uint32_t aB = sb + (uint32_t)s * 16384u;
        const uint32_t bB = sb + 32768u + (uint32_t)s * 16384u;
        #pragma unroll
        for (int ks = 0; ks < 4; ++ks) {
            uint32_t a[4][4], bt[2][4];
            #pragma unroll
            for (int mt = 0; mt < 4; ++mt) ldsm_x4(a[mt], aB + rowOffA[mt] + kx[ks]);
            #pragma unroll
            for (int np = 0; np < 2; ++np) ldsm_x4(bt[np], bB + rowOffB[np] + kx[ks]);
            #pragma unroll
            for (int mt = 0; mt < 4; ++mt)
                #pragma unroll
                for (int nt = 0; nt < 4; ++nt)
                    mma16816(acc[mt][nt], a[mt], bt[nt >> 1][nt & 1], bt[nt >> 1][(nt & 1) + 2]);
        }
        __syncthreads();
    }

    // ---- transform acc in place to logits ----
    const int qr = lane >> 2;            // quad row
    const int qc = (lane & 3) << 1;      // quad col pair base
    #pragma unroll
    for (int mt = 0; mt < 4; ++mt) {
        #pragma unroll
        for (int nt = 0; nt < 4; ++nt) {
            #pragma unroll
            for (int e = 0; e < 4; ++e) {
                const int rl = wm * 64 + mt * 16 + ((e >> 1) << 3) + qr;
                const int cl = wn * 32 + nt * 8 + qc + (e & 1);
                float val = C0 - C1 * (acc[mt][nt][e] + srow[rl] + scol[cl]);
                if (rl == cl) {
                    if (isDiag) {
                        val = NEG_BIG;
                    } else if (isPair) {
                        val += TO_ADD;
                        g_Lpos[rowBase + rl] = val;
                        g_Lpos[colBase + cl] = val;
                    }
                }
                acc[mt][nt][e] = val;
            }
        }
    }

    // ---- row-side LSE (rows of block i; partial slot j) ----
    #pragma unroll
    for (int mt = 0; mt < 4; ++mt) {
        #pragma unroll
        for (int half = 0; half < 2; ++half) {
            const int rl = wm * 64 + mt * 16 + half * 8 + qr;
            float m = NEG_BIG;
            #pragma unroll
            for (int nt = 0; nt < 4; ++nt)
                #pragma unroll
                for (int jj = 0; jj < 2; ++jj)
                    m = fmaxf(m, acc[mt][nt][half * 2 + jj]);
            float su = 0.0f;
            #pragma unroll
            for (int nt = 0; nt < 4; ++nt)
                #pragma unroll
                for (int jj = 0; jj < 2; ++jj)
                    su += __expf(acc[mt][nt][half * 2 + jj] - m);
            #pragma unroll
            for (int o = 1; o < 4; o <<= 1) {
                const float mo = __shfl_xor_sync(0xffffffffu, m, o);
                const float so = __shfl_xor_sync(0xffffffffu, su, o);
                const float nm = fmaxf(m, mo);
                su = su * __expf(m - nm) + so * __expf(mo - nm);
                m = nm;
            }
            if ((lane & 3) == 0) { redM[rl][wn] = m; redS[rl][wn] = su; }
        }
    }

    // ---- col-side LSE (rows of block j; partial slot i) ----
    if (!isDiag) {
        #pragma unroll
        for (int nt = 0; nt < 4; ++nt) {
            #pragma unroll
            for (int jj = 0; jj < 2; ++jj) {
                float m = NEG_BIG;
                #pragma unroll
                for (int mt = 0; mt < 4; ++mt)
                    #pragma unroll
                    for (int half = 0; half < 2; ++half)
                        m = fmaxf(m, acc[mt][nt][half * 2 + jj]);
                float su = 0.0f;
                #pragma unroll
                for (int mt = 0; mt < 4; ++mt)
                    #pragma unroll
                    for (int half = 0; half < 2; ++half)
                        su += __expf(acc[mt][nt][half * 2 + jj] - m);
                #pragma unroll
                for (int o = 4; o < 32; o <<= 1) {
                    const float mo = __shfl_xor_sync(0xffffffffu, m, o);
                    const float so = __shfl_xor_sync(0xffffffffu, su, o);
                    const float nm = fmaxf(m, mo);
                    su = su * __expf(m - nm) + so * __expf(mo - nm);
                    m = nm;
                }
                if (lane < 4) {
                    const int cl = wn * 32 + nt * 8 + qc + jj;
                    redCM[cl][wm] = m;
                    redCS[cl][wm] = su;
                }
            }
        }
    }
    __syncthreads();

    if (tid < 128) {
        // merge row-side across wn
        float M = redM[tid][0], S = redS[tid][0];
        #pragma unroll
        for (int q = 1; q < 4; ++q) {
            const float mj = redM[tid][q], sj = redS[tid][q];
            const float nm = fmaxf(M, mj);
            S = S * __expf(M - nm) + sj * __expf(mj - nm);
            M = nm;
        }
        g_partM[j * NROW + rowBase + tid] = M;
        g_partS[j * NROW + rowBase + tid] = S;

        if (!isDiag) {
            float Mc = redCM[tid][0], Sc = redCS[tid][0];
            const float m1 = redCM[tid][1], s1 = redCS[tid][1];
            const float nm = fmaxf(Mc, m1);
            Sc = Sc * __expf(Mc - nm) + s1 * __expf(m1 - nm);
            Mc = nm;
            g_partM[i * NROW + colBase + tid] = Mc;
            g_partS[i * NROW + colBase + tid] = Sc;
        }
    }
}

// ---------------------------------------------------------------------------
// Kernel 3: merge 32 partials per row -> LSE -> mean(lse - Lpos).
// ---------------------------------------------------------------------------
__global__ void reduce_kernel(float* __restrict__ out) {
    __shared__ float red[256];
    const int tid = threadIdx.x;
    float local = 0.0f;
    for (int row = tid; row < NROW; row += 256) {
        float M = NEG_BIG, S = 0.0f;
        #pragma unroll
        for (int ch = 0; ch < NBLK; ++ch) {
            const float mj = g_partM[ch * NROW + row];
            const float sj = g_partS[ch * NROW + row];
            const float nm = fmaxf(M, mj);
            S = S * expf(M - nm) + sj * expf(mj - nm);
            M = nm;
        }
        local += (M + logf(S)) - g_Lpos[row];
    }
    red[tid] = local;
    __syncthreads();
    #pragma unroll
    for (int off = 128; off > 0; off >>= 1) {
        if (tid < off) red[tid] += red[tid + off];
        __syncthreads();
    }
    if (tid == 0) out[0] = red[0] / (float)NROW;
}

// ---------------------------------------------------------------------------
extern "C" void kernel_launch(void* const* d_in, const int* in_sizes, int n_in,
                              void* d_out, int out_size) {
    (void)in_sizes; (void)n_in; (void)out_size;
    const float* mu_x  = (const float*)d_in[1];
    const float* sig_x = (const float*)d_in[2];
    const float* mu_p  = (const float*)d_in[3];
    const float* sig_p = (const float*)d_in[4];
    float* out = (float*)d_out;

    static bool attr_set = false;
    if (!attr_set) {
        cudaFuncSetAttribute(gemm_kernel, cudaFuncAttributeMaxDynamicSharedMemorySize, 65536);
        attr_set = true;
    }

    feat_kernel<<<NROW / 2, 128>>>(mu_x, sig_x, mu_p, sig_p);
    gemm_kernel<<<NPAIR, 256, 65536>>>();
    reduce_kernel<<<1, 256>>>(out);
}

// round 5
// speedup vs baseline: 5.7055x; 1.2397x over previous
#include <cuda_runtime.h>
#include <cuda_bf16.h>
#include <stdint.h>
#include <math.h>

// ============================================================================
// ContrastiveDistortion:
//   logits[a,b] = C0 - C1*(P_a.Q_b + s_a + s_b)   (rank-512 SYMMETRIC bilinear)
//   fp32 emulated with bf16x3: P' = [Ph|Ph|Pl] (K=1536), Q' = [Qh|Ql|Qh].
// Upper-triangular blocks only (528 CTAs); dual row/col fused online LSE.
// R5: 3-stage cp.async ring, 1 barrier/iter, 2 CTAs/SM.
// ============================================================================

namespace {
constexpr int BATCH = 2048;
constexpr int NROW  = 4096;
constexpr int DIM   = 128;
constexpr int KF3   = 1536;           // 3 * 512
constexpr int NBLK  = 32;             // 4096 / 128
constexpr int NPAIR = NBLK * (NBLK + 1) / 2;   // 528
constexpr int KSTAGES = KF3 / 64;     // 24
constexpr int ROWBYTES = KF3 * 2;     // 3072
constexpr uint32_t STG = 16384u;      // bytes per operand stage

constexpr float C0 = 640.0f;          // D/(2T)
constexpr float C1 = 2.5f;            // 1/(4T)
constexpr float TO_ADD = -1.9538879e-4f;
constexpr float NEG_BIG = -1e30f;
}

__device__ __nv_bfloat16 g_P[(size_t)NROW * KF3];   // 12.6 MB
__device__ __nv_bfloat16 g_Q[(size_t)NROW * KF3];   // 12.6 MB
__device__ float g_s[NROW];
__device__ float g_Lpos[NROW];
__device__ float g_partM[NBLK * NROW];
__device__ float g_partS[NBLK * NROW];

// ---------------------------------------------------------------------------
// helpers
// ---------------------------------------------------------------------------
__device__ __forceinline__ uint32_t smem_u32(const void* p) {
    uint32_t a;
    asm("{ .reg .u64 t; cvta.to.shared.u64 t, %1; cvt.u32.u64 %0, t; }" : "=r"(a) : "l"(p));
    return a;
}
__device__ __forceinline__ void cpasync16(uint32_t dst, const void* src) {
    asm volatile("cp.async.cg.shared.global [%0], [%1], 16;" :: "r"(dst), "l"(src) : "memory");
}
__device__ __forceinline__ void ldsm_x4(uint32_t* r, uint32_t addr) {
    asm volatile("ldmatrix.sync.aligned.m8n8.x4.shared.b16 {%0,%1,%2,%3}, [%4];"
                 : "=r"(r[0]), "=r"(r[1]), "=r"(r[2]), "=r"(r[3]) : "r"(addr));
}
__device__ __forceinline__ void mma16816(float* d, const uint32_t* a, uint32_t b0, uint32_t b1) {
    asm volatile(
        "mma.sync.aligned.m16n8k16.row.col.f32.bf16.bf16.f32 "
        "{%0,%1,%2,%3}, {%4,%5,%6,%7}, {%8,%9}, {%0,%1,%2,%3};"
        : "+f"(d[0]), "+f"(d[1]), "+f"(d[2]), "+f"(d[3])
        : "r"(a[0]), "r"(a[1]), "r"(a[2]), "r"(a[3]), "r"(b0), "r"(b1));
}

// ---------------------------------------------------------------------------
// Kernel 1: build bf16x3 feature rows + row scalars s.
// ---------------------------------------------------------------------------
__global__ void feat_kernel(const float* __restrict__ mu_x,
                            const float* __restrict__ sig_x,
                            const float* __restrict__ mu_p,
                            const float* __restrict__ sig_p) {
    const int t = threadIdx.x;
    const int row = blockIdx.x * 2 + (t >> 6);
    const int d2 = t & 63;

    const float* mu_src = (row < BATCH) ? mu_x + (size_t)row * DIM
                                        : mu_p + (size_t)(row - BATCH) * DIM;
    const float* sg_src = (row < BATCH) ? sig_x + (size_t)row * DIM
                                        : sig_p + (size_t)(row - BATCH) * DIM;
    const float2 mu = *reinterpret_cast<const float2*>(mu_src + 2 * d2);
    const float2 sg = *reinterpret_cast<const float2*>(sg_src + 2 * d2);

    const float var0 = sg.x * sg.x, inv0 = 1.0f / var0;
    const float var1 = sg.y * sg.y, inv1 = 1.0f / var1;
    const float w0 = var0 + mu.x * mu.x, w1 = var1 + mu.y * mu.y;
    const float t0 = mu.x * inv0, t1 = mu.y * inv1;

    const float Pf[4][2] = {{inv0, inv1}, {w0, w1}, {t0, t1}, {mu.x, mu.y}};
    const float Qf[4][2] = {{w0, w1}, {inv0, inv1}, {-2.0f * mu.x, -2.0f * mu.y},
                            {-2.0f * t0, -2.0f * t1}};

    __nv_bfloat16* Prow = g_P + (size_t)row * KF3;
    __nv_bfloat16* Qrow = g_Q + (size_t)row * KF3;

    #pragma unroll
    for (int blk = 0; blk < 4; ++blk) {
        const int k0 = blk * 128 + 2 * d2;
        {
            const float x0 = Pf[blk][0], x1 = Pf[blk][1];
            __nv_bfloat16 h0 = __float2bfloat16(x0), h1 = __float2bfloat16(x1);
            __nv_bfloat16 l0 = __float2bfloat16(x0 - __bfloat162float(h0));
            __nv_bfloat16 l1 = __float2bfloat16(x1 - __bfloat162float(h1));
            __nv_bfloat162 hp = {h0, h1}, lp = {l0, l1};
            const uint32_t hip = *reinterpret_cast<uint32_t*>(&hp);
            const uint32_t lop = *reinterpret_cast<uint32_t*>(&lp);
            *reinterpret_cast<uint32_t*>(Prow +    0 + k0) = hip;
            *reinterpret_cast<uint32_t*>(Prow +  512 + k0) = hip;
            *reinterpret_cast<uint32_t*>(Prow + 1024 + k0) = lop;
        }
        {
            const float x0 = Qf[blk][0], x1 = Qf[blk][1];
            __nv_bfloat16 h0 = __float2bfloat16(x0), h1 = __float2bfloat16(x1);
            __nv_bfloat16 l0 = __float2bfloat16(x0 - __bfloat162float(h0));
            __nv_bfloat16 l1 = __float2bfloat16(x1 - __bfloat162float(h1));
            __nv_bfloat162 hp = {h0, h1}, lp = {l0, l1};
            const uint32_t hip = *reinterpret_cast<uint32_t*>(&hp);
            const uint32_t lop = *reinterpret_cast<uint32_t*>(&lp);
            *reinterpret_cast<uint32_t*>(Qrow +    0 + k0) = hip;
            *reinterpret_cast<uint32_t*>(Qrow +  512 + k0) = lop;
            *reinterpret_cast<uint32_t*>(Qrow + 1024 + k0) = hip;
        }
    }

    float part = t0 * mu.x + t1 * mu.y;
    #pragma unroll
    for (int o = 16; o > 0; o >>= 1) part += __shfl_down_sync(0xffffffffu, part, o);
    __shared__ float ws[4];
    if ((t & 31) == 0) ws[t >> 5] = part;
    __syncthreads();
    if ((t & 63) == 0) g_s[row] = ws[t >> 5] + ws[(t >> 5) + 1];
}

// ---------------------------------------------------------------------------
// Kernel 2: upper-triangular 128x128x1536 bf16 mma.sync GEMM, fused dual LSE.
// grid = 528 pairs (i<=j), 256 threads, 3-stage cp.async ring, 2 CTAs/SM.
// ---------------------------------------------------------------------------
__global__ __launch_bounds__(256, 2) void gemm_kernel() {
    extern __shared__ char smem[];
    __shared__ float scol[128], srow[128];          // pre-scaled: C0/2 - C1*s
    __shared__ float redM[128][4], redS[128][4];    // row-side across wn
    __shared__ float redCM[128][2], redCS[128][2];  // col-side across wm

    const int tid = threadIdx.x;
    const int lane = tid & 31;
    const int warp = tid >> 5;
    const int wm = warp >> 2;
    const int wn = warp & 3;

    // triangular decode: bid -> (i, j), i <= j
    int i = 0, tt = blockIdx.x;
    while (tt >= NBLK - i) { tt -= NBLK - i; ++i; }
    const int j = i + tt;
    const bool isDiag = (i == j);
    const bool isPair = (j == i + 16);
    const int rowBase = i * 128, colBase = j * 128;

    if (tid < 128) {
        srow[tid] = 0.5f * C0 - C1 * g_s[rowBase + tid];
        scol[tid] = 0.5f * C0 - C1 * g_s[colBase + tid];
    }

    const uint32_t sb = smem_u32(smem);
    const char* gA = (const char*)g_P + (size_t)rowBase * ROWBYTES;
    const char* gB = (const char*)g_Q + (size_t)colBase * ROWBYTES;

    float acc[4][4][4];
    #pragma unroll
    for (int mt = 0; mt < 4; ++mt)
        #pragma unroll
        for (int nt = 0; nt < 4; ++nt)
            #pragma unroll
            for (int e = 0; e < 4; ++e) acc[mt][nt][e] = 0.0f;

    const int l15 = lane & 15, lh = lane >> 4;
    const uint32_t xmask = (uint32_t)(lane & 7) << 4;
    uint32_t rowOffA[4], rowOffB[2], kx[4];
    #pragma unroll
    for (int mt = 0; mt < 4; ++mt) rowOffA[mt] = (uint32_t)(wm * 64 + mt * 16 + l15) * 128u;
    #pragma unroll
    for (int np = 0; np < 2; ++np) rowOffB[np] = (uint32_t)(wn * 32 + np * 16 + l15) * 128u;
    #pragma unroll
    for (int ks = 0; ks < 4; ++ks) kx[ks] = ((uint32_t)(ks * 32 + lh * 16)) ^ xmask;

    // stage layout: A stages [0,3*STG), B stages [3*STG, 6*STG)
    auto load_stage = [&](int kt, int s) {
        const uint32_t aD = sb + (uint32_t)s * STG;
        const uint32_t bD = sb + 3u * STG + (uint32_t)s * STG;
        #pragma unroll
        for (int u = 0; u < 4; ++u) {
            const int id = tid + 256 * u;
            const int r = id >> 3, l8 = id & 7;
            const uint32_t doff = (uint32_t)r * 128u + (uint32_t)((l8 ^ (r & 7)) << 4);
            const size_t soff = (size_t)r * ROWBYTES + (size_t)kt * 128 + (size_t)l8 * 16;
            cpasync16(aD + doff, gA + soff);
            cpasync16(bD + doff, gB + soff);
        }
        asm volatile("cp.async.commit_group;" ::: "memory");
    };

    load_stage(0, 0);
    load_stage(1, 1);

    for (int kt = 0; kt < KSTAGES; ++kt) {
        const int s = kt % 3;
        if (kt + 1 < KSTAGES) {
            asm volatile("cp.async.wait_group 1;" ::: "memory");
        } else {
            asm volatile("cp.async.wait_group 0;" ::: "memory");
        }
        __syncthreads();
        // refill the buffer consumed at iteration kt-1
        if (kt + 2 < KSTAGES) load_stage(kt + 2, (kt + 2) % 3);

        const uint32_t aB = sb + (uint32_t)s * STG;
        const uint32_t bB = sb + 3u * STG + (uint32_t)s * STG;
        #pragma unroll
        for (int ks = 0; ks < 4; ++ks) {
            uint32_t a[4][4], bt[2][4];
            #pragma unroll
            for (int mt = 0; mt < 4; ++mt) ldsm_x4(a[mt], aB + rowOffA[mt] + kx[ks]);
            #pragma unroll
            for (int np = 0; np < 2; ++np) ldsm_x4(bt[np], bB + rowOffB[np] + kx[ks]);
            #pragma unroll
            for (int mt = 0; mt < 4; ++mt)
                #pragma unroll
                for (int nt = 0; nt < 4; ++nt)
                    mma16816(acc[mt][nt], a[mt], bt[nt >> 1][nt & 1], bt[nt >> 1][(nt & 1) + 2]);
        }
    }

    // ---- transform acc in place to logits: val = fma(-C1, acc, sr2+sc2) ----
    const int qr = lane >> 2;
    const int qc = (lane & 3) << 1;
    #pragma unroll
    for (int mt = 0; mt < 4; ++mt) {
        #pragma unroll
        for (int nt = 0; nt < 4; ++nt) {
            #pragma unroll
            for (int e = 0; e < 4; ++e) {
                const int rl = wm * 64 + mt * 16 + ((e >> 1) << 3) + qr;
                const int cl = wn * 32 + nt * 8 + qc + (e & 1);
                float val = fmaf(-C1, acc[mt][nt][e], srow[rl] + scol[cl]);
                if (rl == cl) {
                    if (isDiag) {
                        val = NEG_BIG;
                    } else if (isPair) {
                        val += TO_ADD;
                        g_Lpos[rowBase + rl] = val;
                        g_Lpos[colBase + cl] = val;
                    }
                }
                acc[mt][nt][e] = val;
            }
        }
    }

    // ---- row-side LSE (rows of block i; partial slot j) ----
    #pragma unroll
    for (int mt = 0; mt < 4; ++mt) {
        #pragma unroll
        for (int half = 0; half < 2; ++half) {
            const int rl = wm * 64 + mt * 16 + half * 8 + qr;
            float m = NEG_BIG;
            #pragma unroll
            for (int nt = 0; nt < 4; ++nt)
                #pragma unroll
                for (int jj = 0; jj < 2; ++jj)
                    m = fmaxf(m, acc[mt][nt][half * 2 + jj]);
            float su = 0.0f;
            #pragma unroll
            for (int nt = 0; nt < 4; ++nt)
                #pragma unroll
                for (int jj = 0; jj < 2; ++jj)
                    su += __expf(acc[mt][nt][half * 2 + jj] - m);
            #pragma unroll
            for (int o = 1; o < 4; o <<= 1) {
                const float mo = __shfl_xor_sync(0xffffffffu, m, o);
                const float so = __shfl_xor_sync(0xffffffffu, su, o);
                const float nm = fmaxf(m, mo);
                su = su * __expf(m - nm) + so * __expf(mo - nm);
                m = nm;
            }
            if ((lane & 3) == 0) { redM[rl][wn] = m; redS[rl][wn] = su; }
        }
    }

    // ---- col-side LSE (rows of block j; partial slot i) ----
    if (!isDiag) {
        #pragma unroll
        for (int nt = 0; nt < 4; ++nt) {
            #pragma unroll
            for (int jj = 0; jj < 2; ++jj) {
                float m = NEG_BIG;
                #pragma unroll
                for (int mt = 0; mt < 4; ++mt)
                    #pragma unroll
                    for (int half = 0; half < 2; ++half)
                        m = fmaxf(m, acc[mt][nt][half * 2 + jj]);
                float su = 0.0f;
                #pragma unroll
                for (int mt = 0; mt < 4; ++mt)
                    #pragma unroll
                    for (int half = 0; half < 2; ++half)
                        su += __expf(acc[mt][nt][half * 2 + jj] - m);
                #pragma unroll
                for (int o = 4; o < 32; o <<= 1) {
                    const float mo = __shfl_xor_sync(0xffffffffu, m, o);
                    const float so = __shfl_xor_sync(0xffffffffu, su, o);
                    const float nm = fmaxf(m, mo);
                    su = su * __expf(m - nm) + so * __expf(mo - nm);
                    m = nm;
                }
                if (lane < 4) {
                    const int cl = wn * 32 + nt * 8 + qc + jj;
                    redCM[cl][wm] = m;
                    redCS[cl][wm] = su;
                }
            }
        }
    }
    __syncthreads();

    if (tid < 128) {
        float M = redM[tid][0], S = redS[tid][0];
        #pragma unroll
        for (int q = 1; q < 4; ++q) {
            const float mj = redM[tid][q], sj = redS[tid][q];
            const float nm = fmaxf(M, mj);
            S = S * __expf(M - nm) + sj * __expf(mj - nm);
            M = nm;
        }
        g_partM[j * NROW + rowBase + tid] = M;
        g_partS[j * NROW + rowBase + tid] = S;

        if (!isDiag) {
            float Mc = redCM[tid][0], Sc = redCS[tid][0];
            const float m1 = redCM[tid][1], s1 = redCS[tid][1];
            const float nm = fmaxf(Mc, m1);
            Sc = Sc * __expf(Mc - nm) + s1 * __expf(m1 - nm);
            Mc = nm;
            g_partM[i * NROW + colBase + tid] = Mc;
            g_partS[i * NROW + colBase + tid] = Sc;
        }
    }
}

// ---------------------------------------------------------------------------
// Kernel 3: merge 32 partials per row -> LSE -> mean(lse - Lpos).
// ---------------------------------------------------------------------------
__global__ void reduce_kernel(float* __restrict__ out) {
    __shared__ float red[1024];
    const int tid = threadIdx.x;
    float local = 0.0f;
    for (int row = tid; row < NROW; row += 1024) {
        float M = NEG_BIG, S = 0.0f;
        #pragma unroll
        for (int ch = 0; ch < NBLK; ++ch) {
            const float mj = g_partM[ch * NROW + row];
            const float sj = g_partS[ch * NROW + row];
            const float nm = fmaxf(M, mj);
            S = S * expf(M - nm) + sj * expf(mj - nm);
            M = nm;
        }
        local += (M + logf(S)) - g_Lpos[row];
    }
    red[tid] = local;
    __syncthreads();
    #pragma unroll
    for (int off = 512; off > 0; off >>= 1) {
        if (tid < off) red[tid] += red[tid + off];
        __syncthreads();
    }
    if (tid == 0) out[0] = red[0] / (float)NROW;
}

// ---------------------------------------------------------------------------
extern "C" void kernel_launch(void* const* d_in, const int* in_sizes, int n_in,
                              void* d_out, int out_size) {
    (void)in_sizes; (void)n_in; (void)out_size;
    const float* mu_x  = (const float*)d_in[1];
    const float* sig_x = (const float*)d_in[2];
    const float* mu_p  = (const float*)d_in[3];
    const float* sig_p = (const float*)d_in[4];
    float* out = (float*)d_out;

    static bool attr_set = false;
    if (!attr_set) {
        cudaFuncSetAttribute(gemm_kernel, cudaFuncAttributeMaxDynamicSharedMemorySize, 98304);
        attr_set = true;
    }

    feat_kernel<<<NROW / 2, 128>>>(mu_x, sig_x, mu_p, sig_p);
    gemm_kernel<<<NPAIR, 256, 98304>>>();
    reduce_kernel<<<1, 1024>>>(out);
}